// round 12
// baseline (speedup 1.0000x reference)
#include <cuda_runtime.h>
#include <cuda_bf16.h>
#include <cstdint>

#define N_TOK   2048
#define BATCH   64
#define SDIM    512
#define EDIM    512
#define NSPLIT  32
#define CHUNK   (N_TOK / NSPLIT)   // 64
#define NT      8                  // rows per tile (tile = 16 KB)
#define NTILES  (CHUNK / NT)       // 8
#define DEPTH   2                  // cp.async pipeline stages
#define THREADS 128                // each thread owns one float4 of E

// Scratch: partial softmax stats + weighted accumulators per (split, b).
__device__ float g_m[NSPLIT * BATCH];
__device__ float g_l[NSPLIT * BATCH];
__device__ float g_acc[NSPLIT * BATCH * EDIM];   // 4 MiB
__device__ int   g_cnt[BATCH];                   // zero-init; reset after merge

#define CP_ASYNC16(dst_u32, src_ptr) \
    asm volatile("cp.async.cg.shared.global [%0], [%1], 16;\n" \
                 :: "r"(dst_u32), "l"(src_ptr))
#define CP_COMMIT()  asm volatile("cp.async.commit_group;\n" ::: "memory")
#define CP_WAIT_1()  asm volatile("cp.async.wait_group 1;\n" ::: "memory")
#define CP_WAIT_0()  asm volatile("cp.async.wait_group 0;\n" ::: "memory")

// ---------------------------------------------------------------------------
// grid = (NSPLIT, BATCH), block = 128, 6 CTAs/SM.
// GMEM -> smem via cp.async (no RF double buffer -> low regs -> high occ),
// compute structure identical to the measured-good R3 kernel.
// ---------------------------------------------------------------------------
__global__ void __launch_bounds__(THREADS, 6)
attn_fused(const float* __restrict__ emb, const float* __restrict__ W,
           float* __restrict__ out)
{
    const int split = blockIdx.x;
    const int b     = blockIdx.y;
    const int t     = threadIdx.x;          // 0..127
    const int warp  = t >> 5;
    const int lane  = t & 31;

    __shared__ alignas(16) float stage[DEPTH][NT * EDIM];  // 2 x 16 KB
    __shared__ float sh_red[2][4][NT];
    __shared__ int   sh_last;

    // W_e slice for this thread's 4 E-dims.
    const float4 we = reinterpret_cast<const float4*>(W + SDIM)[t];

    float4 acc = make_float4(0.f, 0.f, 0.f, 0.f);
    float  m   = -1e30f;
    float  l   = 0.f;

    const int n0 = split * CHUNK;
    // emb[n,b,e]: float4 row base for (b), stride per n = B*ED/4 = 8192 float4
    const float4* e4 = reinterpret_cast<const float4*>(emb)
                     + (size_t)n0 * (BATCH * (EDIM / 4))
                     + (size_t)b * (EDIM / 4) + t;
    const size_t n_stride = (size_t)BATCH * (EDIM / 4);

    // smem u32 address of this thread's 16B slot in row k of stage s
    const uint32_t st_base = (uint32_t)__cvta_generic_to_shared(&stage[0][0]);

    // --- prologue: issue tile 0 into stage 0 ---
    #pragma unroll
    for (int k = 0; k < NT; k++)
        CP_ASYNC16(st_base + (uint32_t)(k * EDIM + t * 4) * 4u,
                   e4 + (size_t)k * n_stride);
    CP_COMMIT();

    for (int it = 0; it < NTILES; it++) {
        const int cur = it & 1;

        // issue tile it+1 into the other stage, then wait for tile it
        if (it + 1 < NTILES) {
            const uint32_t s_off = (uint32_t)(((it + 1) & 1) * NT * EDIM) * 4u;
            const float4*  g     = e4 + (size_t)(it + 1) * NT * n_stride;
            #pragma unroll
            for (int k = 0; k < NT; k++)
                CP_ASYNC16(st_base + s_off + (uint32_t)(k * EDIM + t * 4) * 4u,
                           g + (size_t)k * n_stride);
            CP_COMMIT();
            CP_WAIT_1();
        } else {
            CP_WAIT_0();
        }
        __syncthreads();                          // tile `it` visible to all

        // read this thread's float4 from each row (conflict-free LDS.128)
        float4 v[NT];
        #pragma unroll
        for (int i = 0; i < NT; i++)
            v[i] = reinterpret_cast<const float4*>(&stage[cur][i * EDIM])[t];

        // partial dots
        float pd[NT];
        #pragma unroll
        for (int i = 0; i < NT; i++)
            pd[i] = v[i].x * we.x + v[i].y * we.y + v[i].z * we.z + v[i].w * we.w;

        // warp reduce all NT dots
        #pragma unroll
        for (int off = 16; off; off >>= 1) {
            #pragma unroll
            for (int i = 0; i < NT; i++)
                pd[i] += __shfl_xor_sync(0xffffffffu, pd[i], off);
        }
        if (lane == 0) {
            #pragma unroll
            for (int i = 0; i < NT; i++)
                sh_red[cur][warp][i] = pd[i];
        }
        __syncthreads();                          // also guards stage reuse

        // every thread finalizes logits + softmax update redundantly
        float lg[NT];
        #pragma unroll
        for (int i = 0; i < NT; i++)
            lg[i] = sh_red[cur][0][i] + sh_red[cur][1][i]
                  + sh_red[cur][2][i] + sh_red[cur][3][i];

        float tm = lg[0];
        #pragma unroll
        for (int i = 1; i < NT; i++) tm = fmaxf(tm, lg[i]);
        const float m_new = fmaxf(m, tm);
        const float scale = __expf(m - m_new);
        m = m_new;
        l *= scale;
        acc.x *= scale; acc.y *= scale; acc.z *= scale; acc.w *= scale;
        #pragma unroll
        for (int i = 0; i < NT; i++) {
            const float p = __expf(lg[i] - m_new);
            l     += p;
            acc.x += p * v[i].x;
            acc.y += p * v[i].y;
            acc.z += p * v[i].z;
            acc.w += p * v[i].w;
        }
    }

    // --- publish partials ---
    const int sb = split * BATCH + b;
    if (t == 0) { g_m[sb] = m; g_l[sb] = l; }
    reinterpret_cast<float4*>(g_acc)[(size_t)sb * (EDIM / 4) + t] = acc;

    // --- last CTA per b merges all splits ---
    __threadfence();
    if (t == 0) {
        int old = atomicAdd(&g_cnt[b], 1);
        sh_last = (old == NSPLIT - 1);
    }
    __syncthreads();
    if (!sh_last) return;
    __threadfence();   // order partial reads after observing the final count

    float M = -1e30f;
    #pragma unroll
    for (int s = 0; s < NSPLIT; s++)
        M = fmaxf(M, g_m[s * BATCH + b]);

    float L = 0.f;
    #pragma unroll
    for (int s = 0; s < NSPLIT; s++)
        L += __expf(g_m[s * BATCH + b] - M) * g_l[s * BATCH + b];
    const float inv = 1.0f / L;

    float4 o = make_float4(0.f, 0.f, 0.f, 0.f);
    #pragma unroll
    for (int s = 0; s < NSPLIT; s++) {
        const float w = __expf(g_m[s * BATCH + b] - M);   // recompute: saves regs
        const float4 a = reinterpret_cast<const float4*>(g_acc)
                             [(size_t)(s * BATCH + b) * (EDIM / 4) + t];
        o.x += w * a.x;
        o.y += w * a.y;
        o.z += w * a.z;
        o.w += w * a.w;
    }
    o.x *= inv; o.y *= inv; o.z *= inv; o.w *= inv;
    reinterpret_cast<float4*>(out)[(size_t)b * (EDIM / 4) + t] = o;

    if (t == 0) g_cnt[b] = 0;   // reset for next replay (graph-deterministic)
}

// ---------------------------------------------------------------------------
// Inputs (metadata order): 0=state_tm1 (B,SD)  1=embeddings (N,B,ED)
//                          2=W (SD+ED,1)       3=b (1,)
// state_tm1 / b / W_s cancel in the softmax over n. Output: (B, ED) f32.
// ---------------------------------------------------------------------------
extern "C" void kernel_launch(void* const* d_in, const int* in_sizes, int n_in,
                              void* d_out, int out_size)
{
    const float* emb = (const float*)d_in[1];
    const float* W   = (const float*)d_in[2];
    float*       out = (float*)d_out;

    dim3 grid(NSPLIT, BATCH);
    attn_fused<<<grid, THREADS>>>(emb, W, out);
}

// round 13
// speedup vs baseline: 1.0322x; 1.0322x over previous
#include <cuda_runtime.h>
#include <cuda_bf16.h>
#include <cstdint>

#define N_TOK   2048
#define BATCH   64
#define SDIM    512
#define EDIM    512
#define NSPLIT  32
#define CHUNK   (N_TOK / NSPLIT)   // 64
#define NT      8                  // rows per tile
#define NTILES  (CHUNK / NT)       // 8
#define THREADS 128
#define NITEMS  (NSPLIT * BATCH)   // 2048 work items
#define GRID    592                // 148 SMs x 4 CTAs, all resident

// Scratch: partial softmax stats + weighted accumulators per (split, b).
__device__ float g_m[NSPLIT * BATCH];
__device__ float g_l[NSPLIT * BATCH];
__device__ float g_acc[NSPLIT * BATCH * EDIM];   // 4 MiB
__device__ int   g_cnt[BATCH];                   // per-b split counter
__device__ int   g_work;                         // work-steal cursor
__device__ int   g_done;                         // exited-CTA counter

// ---------------------------------------------------------------------------
// Persistent kernel: 592 CTAs pop (split,b) items from g_work until drained.
// Item processing = the measured-best R3 mainloop (register double buffer,
// one barrier per tile). Last CTA per b merges the 32 split partials.
// All counters self-reset so every graph replay starts from zero.
// ---------------------------------------------------------------------------
__global__ void __launch_bounds__(THREADS, 4)
attn_persistent(const float* __restrict__ emb, const float* __restrict__ W,
                float* __restrict__ out)
{
    const int t    = threadIdx.x;          // 0..127
    const int warp = t >> 5;
    const int lane = t & 31;

    __shared__ float sh_red[2][4][NT];
    __shared__ int   sh_item;
    __shared__ int   sh_last;

    // W_e slice for this thread's 4 E-dims.
    const float4 we = reinterpret_cast<const float4*>(W + SDIM)[t];
    const size_t n_stride = (size_t)BATCH * (EDIM / 4);

    for (;;) {
        // ---- pop a work item ----
        if (t == 0) sh_item = atomicAdd(&g_work, 1);
        __syncthreads();
        const int item = sh_item;
        __syncthreads();                    // protect sh_item before next pop
        if (item >= NITEMS) break;

        const int split = item / BATCH;     // consecutive items: same n-range,
        const int b     = item % BATCH;     // adjacent b -> DRAM row locality

        float4 acc = make_float4(0.f, 0.f, 0.f, 0.f);
        float  m   = -1e30f;
        float  l   = 0.f;

        const float4* e4 = reinterpret_cast<const float4*>(emb)
                         + (size_t)(split * CHUNK) * n_stride
                         + (size_t)b * (EDIM / 4) + t;

        // --- prologue: load tile 0 ---
        float4 vbuf[2][NT];
        #pragma unroll
        for (int i = 0; i < NT; i++)
            vbuf[0][i] = __ldcs(e4 + (size_t)i * n_stride);

        #pragma unroll 2
        for (int it = 0; it < NTILES; it++) {
            const int cur = it & 1;
            const int nxt = cur ^ 1;

            // partial dots for current tile
            float pd[NT];
            #pragma unroll
            for (int i = 0; i < NT; i++)
                pd[i] = vbuf[cur][i].x * we.x + vbuf[cur][i].y * we.y
                      + vbuf[cur][i].z * we.z + vbuf[cur][i].w * we.w;

            // prefetch next tile — keeps LDGs in flight through the reduction
            if (it + 1 < NTILES) {
                const float4* p = e4 + (size_t)(it + 1) * NT * n_stride;
                #pragma unroll
                for (int i = 0; i < NT; i++)
                    vbuf[nxt][i] = __ldcs(p + (size_t)i * n_stride);
            }

            // warp reduce all NT dots
            #pragma unroll
            for (int off = 16; off; off >>= 1) {
                #pragma unroll
                for (int i = 0; i < NT; i++)
                    pd[i] += __shfl_xor_sync(0xffffffffu, pd[i], off);
            }
            if (lane == 0) {
                #pragma unroll
                for (int i = 0; i < NT; i++)
                    sh_red[cur][warp][i] = pd[i];
            }
            __syncthreads();                 // ONLY barrier this tile

            // every thread finalizes logits + softmax update redundantly
            float lg[NT];
            #pragma unroll
            for (int i = 0; i < NT; i++)
                lg[i] = sh_red[cur][0][i] + sh_red[cur][1][i]
                      + sh_red[cur][2][i] + sh_red[cur][3][i];

            float tm = lg[0];
            #pragma unroll
            for (int i = 1; i < NT; i++) tm = fmaxf(tm, lg[i]);
            const float m_new = fmaxf(m, tm);
            const float scale = __expf(m - m_new);
            m = m_new;
            l *= scale;
            acc.x *= scale; acc.y *= scale; acc.z *= scale; acc.w *= scale;
            #pragma unroll
            for (int i = 0; i < NT; i++) {
                const float p = __expf(lg[i] - m_new);
                l     += p;
                acc.x += p * vbuf[cur][i].x;
                acc.y += p * vbuf[cur][i].y;
                acc.z += p * vbuf[cur][i].z;
                acc.w += p * vbuf[cur][i].w;
            }
        }

        // ---- publish partials ----
        const int sb = split * BATCH + b;
        if (t == 0) { g_m[sb] = m; g_l[sb] = l; }
        reinterpret_cast<float4*>(g_acc)[(size_t)sb * (EDIM / 4) + t] = acc;

        // ---- last CTA per b merges all splits ----
        __threadfence();
        if (t == 0) {
            int old = atomicAdd(&g_cnt[b], 1);
            sh_last = (old == NSPLIT - 1);
        }
        __syncthreads();
        if (sh_last) {
            __threadfence();   // order partial reads after final count

            float M = -1e30f;
            #pragma unroll
            for (int s = 0; s < NSPLIT; s++)
                M = fmaxf(M, g_m[s * BATCH + b]);

            float L = 0.f;
            #pragma unroll
            for (int s = 0; s < NSPLIT; s++)
                L += __expf(g_m[s * BATCH + b] - M) * g_l[s * BATCH + b];
            const float inv = 1.0f / L;

            float4 o = make_float4(0.f, 0.f, 0.f, 0.f);
            #pragma unroll
            for (int s = 0; s < NSPLIT; s++) {
                const float w = __expf(g_m[s * BATCH + b] - M);
                const float4 a = reinterpret_cast<const float4*>(g_acc)
                                     [(size_t)(s * BATCH + b) * (EDIM / 4) + t];
                o.x += w * a.x;
                o.y += w * a.y;
                o.z += w * a.z;
                o.w += w * a.w;
            }
            o.x *= inv; o.y *= inv; o.z *= inv; o.w *= inv;
            reinterpret_cast<float4*>(out)[(size_t)b * (EDIM / 4) + t] = o;

            if (t == 0) g_cnt[b] = 0;       // reset this b's counter
        }
        __syncthreads();                    // sh_red/sh_last safe for reuse
    }

    // ---- last CTA to exit resets the global counters (replay-safe) ----
    __syncthreads();
    if (t == 0) {
        __threadfence();
        int d = atomicAdd(&g_done, 1);
        if (d == GRID - 1) { g_work = 0; g_done = 0; }
    }
}

// ---------------------------------------------------------------------------
// Inputs (metadata order): 0=state_tm1 (B,SD)  1=embeddings (N,B,ED)
//                          2=W (SD+ED,1)       3=b (1,)
// state_tm1 / b / W_s cancel in the softmax over n. Output: (B, ED) f32.
// ---------------------------------------------------------------------------
extern "C" void kernel_launch(void* const* d_in, const int* in_sizes, int n_in,
                              void* d_out, int out_size)
{
    const float* emb = (const float*)d_in[1];
    const float* W   = (const float*)d_in[2];
    float*       out = (float*)d_out;

    attn_persistent<<<GRID, THREADS>>>(emb, W, out);
}